// round 1
// baseline (speedup 1.0000x reference)
#include <cuda_runtime.h>
#include <math.h>

#define DH 1024
#define DM 1024
#define BATCH 128
static constexpr float QK_SCALE = 0.03125f; // 1/sqrt(1024)

// -------- scratch (no allocations allowed) --------
__device__ float g_q[BATCH * DH];
__device__ float g_k[BATCH * DH];
__device__ float g_v[BATCH * DH];
__device__ float g_o[BATCH * DH];
__device__ float g_hh[BATCH * DH];
__device__ float g_ip[BATCH];
__device__ float g_fp[BATCH];
__device__ float g_den[BATCH];

__device__ __forceinline__ float warp_sum(float v) {
    #pragma unroll
    for (int s = 16; s; s >>= 1) v += __shfl_xor_sync(0xffffffffu, v, s);
    return v;
}

// ============================================================
// Projections: Y[b,n] = epilogue( sum_j X[b,j] * W[n,j] )
// grid = (16 n-tiles, 2 m-tiles, 4 matrices), 256 threads
// BM=64, BN=64, BK=16, thread tile 4x4 (strided-16 fragments)
// ============================================================
__global__ void __launch_bounds__(256)
proj_kernel(const float* __restrict__ x,
            const float* __restrict__ Wq, const float* __restrict__ Wk,
            const float* __restrict__ Wv, const float* __restrict__ Wo,
            const float* __restrict__ Wob)
{
    constexpr int BM = 64, BN = 64, BK = 16;
    __shared__ float Xs[BK][BM + 4];
    __shared__ float Ws[BK][BN + 4];

    const int z = blockIdx.z;
    const float* __restrict__ W = (z == 0) ? Wq : (z == 1) ? Wk : (z == 2) ? Wv : Wo;
    float* __restrict__ Y = (z == 0) ? g_q : (z == 1) ? g_k : (z == 2) ? g_v : g_o;

    const int m0 = blockIdx.y * BM;
    const int n0 = blockIdx.x * BN;
    const int tid = threadIdx.x;
    const int tx = tid & 15;
    const int ty = tid >> 4;

    float acc[4][4] = {};

    const int r  = tid >> 2;   // 0..63
    const int c4 = tid & 3;    // 0..3

    for (int k0 = 0; k0 < DM; k0 += BK) {
        float4 xv = *(const float4*)(x + (size_t)(m0 + r) * DM + k0 + c4 * 4);
        float4 wv = *(const float4*)(W + (size_t)(n0 + r) * DM + k0 + c4 * 4);
        Xs[c4 * 4 + 0][r] = xv.x; Xs[c4 * 4 + 1][r] = xv.y;
        Xs[c4 * 4 + 2][r] = xv.z; Xs[c4 * 4 + 3][r] = xv.w;
        Ws[c4 * 4 + 0][r] = wv.x; Ws[c4 * 4 + 1][r] = wv.y;
        Ws[c4 * 4 + 2][r] = wv.z; Ws[c4 * 4 + 3][r] = wv.w;
        __syncthreads();

        #pragma unroll
        for (int k = 0; k < BK; k++) {
            float a[4], w[4];
            #pragma unroll
            for (int i = 0; i < 4; i++) a[i] = Xs[k][i * 16 + ty];
            #pragma unroll
            for (int j = 0; j < 4; j++) w[j] = Ws[k][j * 16 + tx];
            #pragma unroll
            for (int i = 0; i < 4; i++)
                #pragma unroll
                for (int j = 0; j < 4; j++)
                    acc[i][j] = fmaf(a[i], w[j], acc[i][j]);
        }
        __syncthreads();
    }

    #pragma unroll
    for (int i = 0; i < 4; i++) {
        const int m = m0 + i * 16 + ty;
        #pragma unroll
        for (int j = 0; j < 4; j++) {
            const int n = n0 + j * 16 + tx;
            float yv;
            if (z == 3)       yv = 1.f / (1.f + expf(-(acc[i][j] + Wob[n])));
            else if (z == 2)  yv = acc[i][j];
            else              yv = acc[i][j] * QK_SCALE;
            Y[(size_t)m * DH + n] = yv;
        }
    }
}

// ============================================================
// Gating: z_i, z_f, m_t, i', f'   (one block per batch)
// ============================================================
__global__ void __launch_bounds__(256)
gating_kernel(const float* __restrict__ x,
              const float* __restrict__ wi, const float* __restrict__ wib,
              const float* __restrict__ wf, const float* __restrict__ wfb,
              const float* __restrict__ mprev,
              float* __restrict__ out_m)
{
    const int b = blockIdx.x;
    const int t = threadIdx.x;
    const float4 xv = ((const float4*)(x + (size_t)b * DM))[t];
    const float4 iv = ((const float4*)wi)[t];
    const float4 fv = ((const float4*)wf)[t];
    float si = xv.x * iv.x + xv.y * iv.y + xv.z * iv.z + xv.w * iv.w;
    float sf = xv.x * fv.x + xv.y * fv.y + xv.z * fv.z + xv.w * fv.w;

    __shared__ float sbi[8], sbf[8];
    si = warp_sum(si); sf = warp_sum(sf);
    if ((t & 31) == 0) { sbi[t >> 5] = si; sbf[t >> 5] = sf; }
    __syncthreads();
    if (t == 0) {
        float zi = 0.f, zf = 0.f;
        #pragma unroll
        for (int w = 0; w < 8; w++) { zi += sbi[w]; zf += sbf[w]; }
        zi += *wib; zf += *wfb;
        const float mp = mprev[b];
        const float mt = fmaxf(zf + mp, zi);
        out_m[b] = mt;
        g_ip[b] = expf(zi - mt);
        g_fp[b] = expf(zf + mp - mt);
    }
}

// ============================================================
// n_t + denom (one block per batch)
// ============================================================
__global__ void __launch_bounds__(256)
ndenom_kernel(const float* __restrict__ nprev, float* __restrict__ out_n)
{
    const int b = blockIdx.x;
    const int t = threadIdx.x;
    const float f  = g_fp[b];
    const float ip = g_ip[b];
    const float4 np = ((const float4*)(nprev + (size_t)b * DH))[t];
    const float4 kv = ((const float4*)(g_k   + (size_t)b * DH))[t];
    const float4 qv = ((const float4*)(g_q   + (size_t)b * DH))[t];
    float4 n;
    n.x = f * np.x + ip * kv.x;
    n.y = f * np.y + ip * kv.y;
    n.z = f * np.z + ip * kv.z;
    n.w = f * np.w + ip * kv.w;
    ((float4*)(out_n + (size_t)b * DH))[t] = n;

    float s = n.x * qv.x + n.y * qv.y + n.z * qv.z + n.w * qv.w;
    __shared__ float sb[8];
    s = warp_sum(s);
    if ((t & 31) == 0) sb[t >> 5] = s;
    __syncthreads();
    if (t == 0) {
        float tot = 0.f;
        #pragma unroll
        for (int w = 0; w < 8; w++) tot += sb[w];
        g_den[b] = fmaxf(fabsf(tot), 1.f);
    }
}

// ============================================================
// Fused C update + Cq matvec + h_head  (the HBM-bound kernel)
// grid = (128 row-chunks, 128 batches), 256 threads = 8 warps
// warp w handles row i = bx*8 + w : streams 4 KB of C_prev in,
// 4 KB of C_t out, dot-accumulates against q in registers.
// ============================================================
__global__ void __launch_bounds__(256)
c_update_kernel(const float* __restrict__ Cprev, float* __restrict__ Cout)
{
    const int b = blockIdx.y;
    __shared__ float4 ks4[256];
    __shared__ float4 qs4[256];
    for (int t = threadIdx.x; t < 256; t += 256) {
        ks4[t] = ((const float4*)(g_k + (size_t)b * DH))[t];
        qs4[t] = ((const float4*)(g_q + (size_t)b * DH))[t];
    }
    __syncthreads();

    const int warp = threadIdx.x >> 5;
    const int lane = threadIdx.x & 31;
    const int i = blockIdx.x * 8 + warp;

    const float f  = g_fp[b];
    const float iv = g_ip[b] * g_v[(size_t)b * DH + i];

    const float4* __restrict__ cp = (const float4*)(Cprev + ((size_t)b * DH + i) * DH);
    float4* __restrict__ co = (float4*)(Cout + ((size_t)b * DH + i) * DH);

    float acc = 0.f;
    #pragma unroll
    for (int u = 0; u < 8; u++) {
        const int j4 = u * 32 + lane;
        const float4 c4 = __ldcs(&cp[j4]);   // streaming: no reuse
        const float4 k4 = ks4[j4];
        const float4 q4 = qs4[j4];
        float4 o;
        o.x = fmaf(f, c4.x, iv * k4.x);
        o.y = fmaf(f, c4.y, iv * k4.y);
        o.z = fmaf(f, c4.z, iv * k4.z);
        o.w = fmaf(f, c4.w, iv * k4.w);
        acc = fmaf(o.x, q4.x, acc);
        acc = fmaf(o.y, q4.y, acc);
        acc = fmaf(o.z, q4.z, acc);
        acc = fmaf(o.w, q4.w, acc);
        __stcs(&co[j4], o);
    }
    acc = warp_sum(acc);
    if (lane == 0)
        g_hh[(size_t)b * DH + i] = g_o[(size_t)b * DH + i] * acc / g_den[b];
}

// ============================================================
// out_proj: h_t[b,m] = sum_d hh[b,d] * P[m,d]
// grid = (32 n-tiles, 4 m-tiles), BM=32, BN=32, BK=16, tile 2x2
// ============================================================
__global__ void __launch_bounds__(256)
outproj_kernel(const float* __restrict__ P, float* __restrict__ out_h)
{
    constexpr int BM = 32, BN = 32, BK = 16;
    __shared__ float Xs[BK][BM + 4];
    __shared__ float Ws[BK][BN + 4];

    const int m0 = blockIdx.y * BM;
    const int n0 = blockIdx.x * BN;
    const int tid = threadIdx.x;
    const int tx = tid & 15;
    const int ty = tid >> 4;

    float acc[2][2] = {};

    for (int k0 = 0; k0 < DH; k0 += BK) {
        if (tid < 128) {
            const int r = tid >> 2, c4 = tid & 3;
            float4 v = *(const float4*)(g_hh + (size_t)(m0 + r) * DH + k0 + c4 * 4);
            Xs[c4 * 4 + 0][r] = v.x; Xs[c4 * 4 + 1][r] = v.y;
            Xs[c4 * 4 + 2][r] = v.z; Xs[c4 * 4 + 3][r] = v.w;
        } else {
            const int idx = tid - 128;
            const int r = idx >> 2, c4 = idx & 3;
            float4 v = *(const float4*)(P + (size_t)(n0 + r) * DH + k0 + c4 * 4);
            Ws[c4 * 4 + 0][r] = v.x; Ws[c4 * 4 + 1][r] = v.y;
            Ws[c4 * 4 + 2][r] = v.z; Ws[c4 * 4 + 3][r] = v.w;
        }
        __syncthreads();

        #pragma unroll
        for (int k = 0; k < BK; k++) {
            float a[2], w[2];
            #pragma unroll
            for (int i = 0; i < 2; i++) a[i] = Xs[k][i * 16 + ty];
            #pragma unroll
            for (int j = 0; j < 2; j++) w[j] = Ws[k][j * 16 + tx];
            #pragma unroll
            for (int i = 0; i < 2; i++)
                #pragma unroll
                for (int j = 0; j < 2; j++)
                    acc[i][j] = fmaf(a[i], w[j], acc[i][j]);
        }
        __syncthreads();
    }

    #pragma unroll
    for (int i = 0; i < 2; i++) {
        const int m = m0 + i * 16 + ty;
        #pragma unroll
        for (int j = 0; j < 2; j++) {
            const int n = n0 + j * 16 + tx;
            out_h[(size_t)m * DM + n] = acc[i][j];
        }
    }
}

// ============================================================
// launch
// ============================================================
extern "C" void kernel_launch(void* const* d_in, const int* in_sizes, int n_in,
                              void* d_out, int out_size)
{
    const float* x     = (const float*)d_in[0];
    const float* Cprev = (const float*)d_in[1];
    const float* nprev = (const float*)d_in[2];
    const float* mprev = (const float*)d_in[3];
    const float* Wq    = (const float*)d_in[4];
    const float* Wk    = (const float*)d_in[5];
    const float* Wv    = (const float*)d_in[6];
    const float* wi    = (const float*)d_in[7];
    const float* wib   = (const float*)d_in[8];
    const float* wf    = (const float*)d_in[9];
    const float* wfb   = (const float*)d_in[10];
    const float* Wo    = (const float*)d_in[11];
    const float* Wob   = (const float*)d_in[12];
    const float* P     = (const float*)d_in[13];

    float* out   = (float*)d_out;
    float* out_h = out;                                        // (B, 1024)
    float* out_c = out + (size_t)BATCH * DM;                   // (B, 1024, 1024)
    float* out_n = out_c + (size_t)BATCH * DH * DH;            // (B, 1024)
    float* out_m = out_n + (size_t)BATCH * DH;                 // (B,)

    proj_kernel<<<dim3(16, 2, 4), 256>>>(x, Wq, Wk, Wv, Wo, Wob);
    gating_kernel<<<BATCH, 256>>>(x, wi, wib, wf, wfb, mprev, out_m);
    ndenom_kernel<<<BATCH, 256>>>(nprev, out_n);
    c_update_kernel<<<dim3(128, BATCH), 256>>>(Cprev, out_c);
    outproj_kernel<<<dim3(32, 4), 256>>>(P, out_h);
}

// round 3
// speedup vs baseline: 1.2885x; 1.2885x over previous
#include <cuda_runtime.h>
#include <math.h>

#define DH 1024
#define DM 1024
#define BATCH 128
static constexpr float QK_SCALE = 0.03125f; // 1/sqrt(1024)

// -------- scratch (no allocations allowed) --------
__device__ float g_q[BATCH * DH];
__device__ float g_k[BATCH * DH];
__device__ float g_v[BATCH * DH];
__device__ float g_o[BATCH * DH];
__device__ float g_hh[BATCH * DH];
__device__ float g_part[4][BATCH * DM];   // split-K partials for out_proj
__device__ float g_ip[BATCH];
__device__ float g_fp[BATCH];
__device__ float g_den[BATCH];

__device__ __forceinline__ float warp_sum(float v) {
    #pragma unroll
    for (int s = 16; s; s >>= 1) v += __shfl_xor_sync(0xffffffffu, v, s);
    return v;
}

// ============================================================
// Shared GEMM core: acc[4][4] += X[m0+..,k] * W[n0+..,k]
// BM=BN=64, BK=16, 256 threads, contiguous 4x4 thread tile,
// double-buffered smem, fragments via LDS.128.
// ============================================================
#define SMS 68  // smem row stride (floats): 68*4B = 272B, 16B-aligned, depads banks

__device__ __forceinline__ void gemm_tile(
    const float* __restrict__ X, const float* __restrict__ W,
    int m0, int n0, int kbeg, int ktiles,
    float (&Xs)[2][16][SMS], float (&Ws)[2][16][SMS],
    float (&acc)[4][4])
{
    const int tid = threadIdx.x;
    const int r   = tid >> 2;   // 0..63
    const int c4  = tid & 3;    // 0..3
    const int tx  = tid & 15;   // n-frag
    const int ty  = tid >> 4;   // m-frag

    const float* __restrict__ xg = X + (size_t)(m0 + r) * DM + kbeg + c4 * 4;
    const float* __restrict__ wg = W + (size_t)(n0 + r) * DM + kbeg + c4 * 4;

    float4 xv = *(const float4*)xg;
    float4 wv = *(const float4*)wg;

    int buf = 0;
    Xs[0][c4 * 4 + 0][r] = xv.x; Xs[0][c4 * 4 + 1][r] = xv.y;
    Xs[0][c4 * 4 + 2][r] = xv.z; Xs[0][c4 * 4 + 3][r] = xv.w;
    Ws[0][c4 * 4 + 0][r] = wv.x; Ws[0][c4 * 4 + 1][r] = wv.y;
    Ws[0][c4 * 4 + 2][r] = wv.z; Ws[0][c4 * 4 + 3][r] = wv.w;
    __syncthreads();

    for (int kt = 0; kt < ktiles; kt++) {
        if (kt + 1 < ktiles) {
            xv = *(const float4*)(xg + (kt + 1) * 16);
            wv = *(const float4*)(wg + (kt + 1) * 16);
        }
        #pragma unroll
        for (int k = 0; k < 16; k++) {
            const float4 a = *(const float4*)&Xs[buf][k][ty * 4];
            const float4 w = *(const float4*)&Ws[buf][k][tx * 4];
            acc[0][0] = fmaf(a.x, w.x, acc[0][0]); acc[0][1] = fmaf(a.x, w.y, acc[0][1]);
            acc[0][2] = fmaf(a.x, w.z, acc[0][2]); acc[0][3] = fmaf(a.x, w.w, acc[0][3]);
            acc[1][0] = fmaf(a.y, w.x, acc[1][0]); acc[1][1] = fmaf(a.y, w.y, acc[1][1]);
            acc[1][2] = fmaf(a.y, w.z, acc[1][2]); acc[1][3] = fmaf(a.y, w.w, acc[1][3]);
            acc[2][0] = fmaf(a.z, w.x, acc[2][0]); acc[2][1] = fmaf(a.z, w.y, acc[2][1]);
            acc[2][2] = fmaf(a.z, w.z, acc[2][2]); acc[2][3] = fmaf(a.z, w.w, acc[2][3]);
            acc[3][0] = fmaf(a.w, w.x, acc[3][0]); acc[3][1] = fmaf(a.w, w.y, acc[3][1]);
            acc[3][2] = fmaf(a.w, w.z, acc[3][2]); acc[3][3] = fmaf(a.w, w.w, acc[3][3]);
        }
        if (kt + 1 < ktiles) {
            const int nb = buf ^ 1;
            Xs[nb][c4 * 4 + 0][r] = xv.x; Xs[nb][c4 * 4 + 1][r] = xv.y;
            Xs[nb][c4 * 4 + 2][r] = xv.z; Xs[nb][c4 * 4 + 3][r] = xv.w;
            Ws[nb][c4 * 4 + 0][r] = wv.x; Ws[nb][c4 * 4 + 1][r] = wv.y;
            Ws[nb][c4 * 4 + 2][r] = wv.z; Ws[nb][c4 * 4 + 3][r] = wv.w;
            __syncthreads();
            buf = nb;
        }
    }
}

// ============================================================
// Projections q/k/v/sigmoid(o): grid (16 n, 2 m, 4 mat), 256 thr
// ============================================================
__global__ void __launch_bounds__(256)
proj_kernel(const float* __restrict__ x,
            const float* __restrict__ Wq, const float* __restrict__ Wk,
            const float* __restrict__ Wv, const float* __restrict__ Wo,
            const float* __restrict__ Wob)
{
    __shared__ float Xs[2][16][SMS];
    __shared__ float Ws[2][16][SMS];

    const int z = blockIdx.z;
    const float* __restrict__ W = (z == 0) ? Wq : (z == 1) ? Wk : (z == 2) ? Wv : Wo;
    float* __restrict__ Y = (z == 0) ? g_q : (z == 1) ? g_k : (z == 2) ? g_v : g_o;

    const int m0 = blockIdx.y * 64;
    const int n0 = blockIdx.x * 64;
    const int tx = threadIdx.x & 15;
    const int ty = threadIdx.x >> 4;

    float acc[4][4] = {};
    gemm_tile(x, W, m0, n0, 0, 64, Xs, Ws, acc);

    #pragma unroll
    for (int i = 0; i < 4; i++) {
        const int m = m0 + ty * 4 + i;
        const int nb = n0 + tx * 4;
        float4 y;
        if (z == 3) {
            y.x = 1.f / (1.f + expf(-(acc[i][0] + Wob[nb + 0])));
            y.y = 1.f / (1.f + expf(-(acc[i][1] + Wob[nb + 1])));
            y.z = 1.f / (1.f + expf(-(acc[i][2] + Wob[nb + 2])));
            y.w = 1.f / (1.f + expf(-(acc[i][3] + Wob[nb + 3])));
        } else if (z == 2) {
            y.x = acc[i][0]; y.y = acc[i][1]; y.z = acc[i][2]; y.w = acc[i][3];
        } else {
            y.x = acc[i][0] * QK_SCALE; y.y = acc[i][1] * QK_SCALE;
            y.z = acc[i][2] * QK_SCALE; y.w = acc[i][3] * QK_SCALE;
        }
        *(float4*)&Y[(size_t)m * DH + nb] = y;
    }
}

// ============================================================
// out_proj split-K: grid (16 n, 2 m, 4 ksplit) -> partials
// ============================================================
__global__ void __launch_bounds__(256)
outproj_kernel(const float* __restrict__ P)
{
    __shared__ float Xs[2][16][SMS];
    __shared__ float Ws[2][16][SMS];

    const int z  = blockIdx.z;           // K split index
    const int m0 = blockIdx.y * 64;
    const int n0 = blockIdx.x * 64;
    const int tx = threadIdx.x & 15;
    const int ty = threadIdx.x >> 4;

    float acc[4][4] = {};
    gemm_tile(g_hh, P, m0, n0, z * 256, 16, Xs, Ws, acc);

    float* __restrict__ Yp = g_part[z];
    #pragma unroll
    for (int i = 0; i < 4; i++) {
        const int m = m0 + ty * 4 + i;
        const int nb = n0 + tx * 4;
        float4 y;
        y.x = acc[i][0]; y.y = acc[i][1]; y.z = acc[i][2]; y.w = acc[i][3];
        *(float4*)&Yp[(size_t)m * DM + nb] = y;
    }
}

__global__ void __launch_bounds__(256)
outproj_reduce_kernel(float* __restrict__ out_h)
{
    const int idx = blockIdx.x * 256 + threadIdx.x; // float4 index
    const float4 a = ((const float4*)g_part[0])[idx];
    const float4 b = ((const float4*)g_part[1])[idx];
    const float4 c = ((const float4*)g_part[2])[idx];
    const float4 d = ((const float4*)g_part[3])[idx];
    float4 r;
    r.x = (a.x + b.x) + (c.x + d.x);
    r.y = (a.y + b.y) + (c.y + d.y);
    r.z = (a.z + b.z) + (c.z + d.z);
    r.w = (a.w + b.w) + (c.w + d.w);
    ((float4*)out_h)[idx] = r;
}

// ============================================================
// Gating: z_i, z_f, m_t, i', f'   (one block per batch)
// ============================================================
__global__ void __launch_bounds__(256)
gating_kernel(const float* __restrict__ x,
              const float* __restrict__ wi, const float* __restrict__ wib,
              const float* __restrict__ wf, const float* __restrict__ wfb,
              const float* __restrict__ mprev,
              float* __restrict__ out_m)
{
    const int b = blockIdx.x;
    const int t = threadIdx.x;
    const float4 xv = ((const float4*)(x + (size_t)b * DM))[t];
    const float4 iv = ((const float4*)wi)[t];
    const float4 fv = ((const float4*)wf)[t];
    float si = xv.x * iv.x + xv.y * iv.y + xv.z * iv.z + xv.w * iv.w;
    float sf = xv.x * fv.x + xv.y * fv.y + xv.z * fv.z + xv.w * fv.w;

    __shared__ float sbi[8], sbf[8];
    si = warp_sum(si); sf = warp_sum(sf);
    if ((t & 31) == 0) { sbi[t >> 5] = si; sbf[t >> 5] = sf; }
    __syncthreads();
    if (t == 0) {
        float zi = 0.f, zf = 0.f;
        #pragma unroll
        for (int w = 0; w < 8; w++) { zi += sbi[w]; zf += sbf[w]; }
        zi += *wib; zf += *wfb;
        const float mp = mprev[b];
        const float mt = fmaxf(zf + mp, zi);
        out_m[b] = mt;
        g_ip[b] = expf(zi - mt);
        g_fp[b] = expf(zf + mp - mt);
    }
}

// ============================================================
// n_t + denom (one block per batch)
// ============================================================
__global__ void __launch_bounds__(256)
ndenom_kernel(const float* __restrict__ nprev, float* __restrict__ out_n)
{
    const int b = blockIdx.x;
    const int t = threadIdx.x;
    const float f  = g_fp[b];
    const float ip = g_ip[b];
    const float4 np = ((const float4*)(nprev + (size_t)b * DH))[t];
    const float4 kv = ((const float4*)(g_k   + (size_t)b * DH))[t];
    const float4 qv = ((const float4*)(g_q   + (size_t)b * DH))[t];
    float4 n;
    n.x = f * np.x + ip * kv.x;
    n.y = f * np.y + ip * kv.y;
    n.z = f * np.z + ip * kv.z;
    n.w = f * np.w + ip * kv.w;
    ((float4*)(out_n + (size_t)b * DH))[t] = n;

    float s = n.x * qv.x + n.y * qv.y + n.z * qv.z + n.w * qv.w;
    __shared__ float sb[8];
    s = warp_sum(s);
    if ((t & 31) == 0) sb[t >> 5] = s;
    __syncthreads();
    if (t == 0) {
        float tot = 0.f;
        #pragma unroll
        for (int w = 0; w < 8; w++) tot += sb[w];
        g_den[b] = fmaxf(fabsf(tot), 1.f);
    }
}

// ============================================================
// Fused C update + Cq matvec + h_head  (HBM-bound)
// grid (128 row-chunks, 128 batches), 256 threads = 8 warps.
// Warp w owns row i: batch all 8 LDG.128.cs first (MLP=8),
// then FMA + streaming stores + warp-reduced dot with q.
// ============================================================
__global__ void __launch_bounds__(256)
c_update_kernel(const float* __restrict__ Cprev, float* __restrict__ Cout)
{
    const int b = blockIdx.y;
    __shared__ float4 ks4[256];
    __shared__ float4 qs4[256];
    {
        const int t = threadIdx.x;
        ks4[t] = ((const float4*)(g_k + (size_t)b * DH))[t];
        qs4[t] = ((const float4*)(g_q + (size_t)b * DH))[t];
    }
    __syncthreads();

    const int warp = threadIdx.x >> 5;
    const int lane = threadIdx.x & 31;
    const int i = blockIdx.x * 8 + warp;

    const float f  = g_fp[b];
    const float iv = g_ip[b] * g_v[(size_t)b * DH + i];

    const float4* __restrict__ cp = (const float4*)(Cprev + ((size_t)b * DH + i) * DH);
    float4* __restrict__ co = (float4*)(Cout + ((size_t)b * DH + i) * DH);

    float4 c[8];
    #pragma unroll
    for (int u = 0; u < 8; u++) c[u] = __ldcs(&cp[u * 32 + lane]);

    float acc = 0.f;
    #pragma unroll
    for (int u = 0; u < 8; u++) {
        const int j4 = u * 32 + lane;
        const float4 k4 = ks4[j4];
        const float4 q4 = qs4[j4];
        float4 o;
        o.x = fmaf(f, c[u].x, iv * k4.x);
        o.y = fmaf(f, c[u].y, iv * k4.y);
        o.z = fmaf(f, c[u].z, iv * k4.z);
        o.w = fmaf(f, c[u].w, iv * k4.w);
        acc = fmaf(o.x, q4.x, acc);
        acc = fmaf(o.y, q4.y, acc);
        acc = fmaf(o.z, q4.z, acc);
        acc = fmaf(o.w, q4.w, acc);
        __stcs(&co[j4], o);
    }
    acc = warp_sum(acc);
    if (lane == 0)
        g_hh[(size_t)b * DH + i] = g_o[(size_t)b * DH + i] * acc / g_den[b];
}

// ============================================================
// launch
// ============================================================
extern "C" void kernel_launch(void* const* d_in, const int* in_sizes, int n_in,
                              void* d_out, int out_size)
{
    const float* x     = (const float*)d_in[0];
    const float* Cprev = (const float*)d_in[1];
    const float* nprev = (const float*)d_in[2];
    const float* mprev = (const float*)d_in[3];
    const float* Wq    = (const float*)d_in[4];
    const float* Wk    = (const float*)d_in[5];
    const float* Wv    = (const float*)d_in[6];
    const float* wi    = (const float*)d_in[7];
    const float* wib   = (const float*)d_in[8];
    const float* wf    = (const float*)d_in[9];
    const float* wfb   = (const float*)d_in[10];
    const float* Wo    = (const float*)d_in[11];
    const float* Wob   = (const float*)d_in[12];
    const float* P     = (const float*)d_in[13];

    float* out   = (float*)d_out;
    float* out_h = out;                                        // (B, 1024)
    float* out_c = out + (size_t)BATCH * DM;                   // (B, 1024, 1024)
    float* out_n = out_c + (size_t)BATCH * DH * DH;            // (B, 1024)
    float* out_m = out_n + (size_t)BATCH * DH;                 // (B,)

    gating_kernel<<<BATCH, 256>>>(x, wi, wib, wf, wfb, mprev, out_m);
    proj_kernel<<<dim3(16, 2, 4), 256>>>(x, Wq, Wk, Wv, Wo, Wob);
    ndenom_kernel<<<BATCH, 256>>>(nprev, out_n);
    c_update_kernel<<<dim3(128, BATCH), 256>>>(Cprev, out_c);
    outproj_kernel<<<dim3(16, 2, 4), 256>>>(P);
    outproj_reduce_kernel<<<128, 256>>>(out_h);
}

// round 5
// speedup vs baseline: 1.2971x; 1.0066x over previous
#include <cuda_runtime.h>
#include <math.h>

#define DH 1024
#define DM 1024
#define BATCH 128
static constexpr float QK_SCALE = 0.03125f; // 1/sqrt(1024)

// -------- scratch (no allocations allowed) --------
__device__ float g_q[BATCH * DH];
__device__ float g_k[BATCH * DH];
__device__ float g_v[BATCH * DH];
__device__ float g_o[BATCH * DH];
__device__ float g_hh[BATCH * DH];
__device__ float g_part[4][BATCH * DM];   // split-K partials for out_proj
__device__ float g_ip[BATCH];
__device__ float g_fp[BATCH];
__device__ float g_den[BATCH];

__device__ __forceinline__ float warp_sum(float v) {
    #pragma unroll
    for (int s = 16; s; s >>= 1) v += __shfl_xor_sync(0xffffffffu, v, s);
    return v;
}

// ============================================================
// Projections q/k/v/sigmoid(o)
// BM=64, BN=32, BK=16, 128 threads, 4x4 thread tile.
// grid = (32 n-tiles, 2 m-tiles, 4 matrices) = 256 blocks.
// Double-buffered smem, fragments via LDS.128.
// ============================================================
#define SMS 68  // smem row stride in floats (16B aligned, conflict-free)

__global__ void __launch_bounds__(128)
proj_kernel(const float* __restrict__ x,
            const float* __restrict__ Wq, const float* __restrict__ Wk,
            const float* __restrict__ Wv, const float* __restrict__ Wo,
            const float* __restrict__ Wob)
{
    __shared__ float Xs[2][16][SMS];      // 64 m-rows
    __shared__ float Ws[2][16][36];       // 32 n-rows

    const int z = blockIdx.z;
    const float* __restrict__ W = (z == 0) ? Wq : (z == 1) ? Wk : (z == 2) ? Wv : Wo;
    float* __restrict__ Y = (z == 0) ? g_q : (z == 1) ? g_k : (z == 2) ? g_v : g_o;

    const int m0 = blockIdx.y * 64;
    const int n0 = blockIdx.x * 32;
    const int tid = threadIdx.x;
    const int tx = tid & 7;               // 0..7  -> n frag (4 cols)
    const int ty = tid >> 3;              // 0..15 -> m frag (4 rows)

    // loaders: X: 64 rows x 16 cols, 128 threads -> each loads 2 rows x float4... 
    // r = tid>>1 (0..63), c4 = tid&1 -> 2 float4 per row? 64*16/4=256 float4, 128 thr -> 2 each
    const int xr = tid >> 1;              // 0..63
    const int xc = tid & 1;               // 0..1 (float4 col pair: 2 x 8 floats)
    const int wr = tid >> 2;              // 0..31
    const int wc = tid & 3;               // 0..3

    const float* __restrict__ xg = x + (size_t)(m0 + xr) * DM + xc * 8;
    const float* __restrict__ wg = W + (size_t)(n0 + wr) * DM + wc * 4;

    float4 xv0 = *(const float4*)xg;
    float4 xv1 = *(const float4*)(xg + 4);
    float4 wv  = *(const float4*)wg;

    float acc[4][4] = {};
    int buf = 0;

    #pragma unroll 1
    for (int kt = 0; kt < 64; kt++) {
        // stage current
        {
            const int cb = xc * 8;
            Xs[buf][cb + 0][xr] = xv0.x; Xs[buf][cb + 1][xr] = xv0.y;
            Xs[buf][cb + 2][xr] = xv0.z; Xs[buf][cb + 3][xr] = xv0.w;
            Xs[buf][cb + 4][xr] = xv1.x; Xs[buf][cb + 5][xr] = xv1.y;
            Xs[buf][cb + 6][xr] = xv1.z; Xs[buf][cb + 7][xr] = xv1.w;
            Ws[buf][wc * 4 + 0][wr] = wv.x; Ws[buf][wc * 4 + 1][wr] = wv.y;
            Ws[buf][wc * 4 + 2][wr] = wv.z; Ws[buf][wc * 4 + 3][wr] = wv.w;
        }
        __syncthreads();
        if (kt + 1 < 64) {
            xv0 = *(const float4*)(xg + (kt + 1) * 16);
            xv1 = *(const float4*)(xg + (kt + 1) * 16 + 4);
            wv  = *(const float4*)(wg + (kt + 1) * 16);
        }
        #pragma unroll
        for (int k = 0; k < 16; k++) {
            const float4 a = *(const float4*)&Xs[buf][k][ty * 4];
            const float4 w = *(const float4*)&Ws[buf][k][tx * 4];
            acc[0][0] = fmaf(a.x, w.x, acc[0][0]); acc[0][1] = fmaf(a.x, w.y, acc[0][1]);
            acc[0][2] = fmaf(a.x, w.z, acc[0][2]); acc[0][3] = fmaf(a.x, w.w, acc[0][3]);
            acc[1][0] = fmaf(a.y, w.x, acc[1][0]); acc[1][1] = fmaf(a.y, w.y, acc[1][1]);
            acc[1][2] = fmaf(a.y, w.z, acc[1][2]); acc[1][3] = fmaf(a.y, w.w, acc[1][3]);
            acc[2][0] = fmaf(a.z, w.x, acc[2][0]); acc[2][1] = fmaf(a.z, w.y, acc[2][1]);
            acc[2][2] = fmaf(a.z, w.z, acc[2][2]); acc[2][3] = fmaf(a.z, w.w, acc[2][3]);
            acc[3][0] = fmaf(a.w, w.x, acc[3][0]); acc[3][1] = fmaf(a.w, w.y, acc[3][1]);
            acc[3][2] = fmaf(a.w, w.z, acc[3][2]); acc[3][3] = fmaf(a.w, w.w, acc[3][3]);
        }
        __syncthreads();
        buf ^= 1;
    }

    #pragma unroll
    for (int i = 0; i < 4; i++) {
        const int m = m0 + ty * 4 + i;
        const int nb = n0 + tx * 4;
        float4 y;
        if (z == 3) {
            y.x = 1.f / (1.f + expf(-(acc[i][0] + Wob[nb + 0])));
            y.y = 1.f / (1.f + expf(-(acc[i][1] + Wob[nb + 1])));
            y.z = 1.f / (1.f + expf(-(acc[i][2] + Wob[nb + 2])));
            y.w = 1.f / (1.f + expf(-(acc[i][3] + Wob[nb + 3])));
        } else if (z == 2) {
            y.x = acc[i][0]; y.y = acc[i][1]; y.z = acc[i][2]; y.w = acc[i][3];
        } else {
            y.x = acc[i][0] * QK_SCALE; y.y = acc[i][1] * QK_SCALE;
            y.z = acc[i][2] * QK_SCALE; y.w = acc[i][3] * QK_SCALE;
        }
        *(float4*)&Y[(size_t)m * DH + nb] = y;
    }
}

// ============================================================
// Merged gating + n_t + denom (one block per batch, 256 thr)
//   z_i = x.wi + bi ; z_f = x.wf + bf
//   m_t = max(z_f + m_prev, z_i); i'=exp(zi-mt); f'=exp(zf+mp-mt)
//   n_t = f'*n_prev + i'*k ; den = max(|n_t.q|, 1)
// ============================================================
__global__ void __launch_bounds__(256)
gate_ndenom_kernel(const float* __restrict__ x,
                   const float* __restrict__ wi, const float* __restrict__ wib,
                   const float* __restrict__ wf, const float* __restrict__ wfb,
                   const float* __restrict__ mprev,
                   const float* __restrict__ nprev,
                   float* __restrict__ out_m, float* __restrict__ out_n)
{
    const int b = blockIdx.x;
    const int t = threadIdx.x;

    const float4 xv = ((const float4*)(x + (size_t)b * DM))[t];
    const float4 iv = ((const float4*)wi)[t];
    const float4 fv = ((const float4*)wf)[t];
    float si = xv.x * iv.x + xv.y * iv.y + xv.z * iv.z + xv.w * iv.w;
    float sf = xv.x * fv.x + xv.y * fv.y + xv.z * fv.z + xv.w * fv.w;

    __shared__ float sbi[8], sbf[8], sgate[2];
    si = warp_sum(si); sf = warp_sum(sf);
    if ((t & 31) == 0) { sbi[t >> 5] = si; sbf[t >> 5] = sf; }
    __syncthreads();
    if (t == 0) {
        float zi = 0.f, zf = 0.f;
        #pragma unroll
        for (int w = 0; w < 8; w++) { zi += sbi[w]; zf += sbf[w]; }
        zi += *wib; zf += *wfb;
        const float mp = mprev[b];
        const float mt = fmaxf(zf + mp, zi);
        const float ip = expf(zi - mt);
        const float fp = expf(zf + mp - mt);
        out_m[b] = mt;
        g_ip[b] = ip; g_fp[b] = fp;
        sgate[0] = ip; sgate[1] = fp;
    }
    __syncthreads();

    const float ip = sgate[0];
    const float f  = sgate[1];
    const float4 np = ((const float4*)(nprev + (size_t)b * DH))[t];
    const float4 kv = ((const float4*)(g_k   + (size_t)b * DH))[t];
    const float4 qv = ((const float4*)(g_q   + (size_t)b * DH))[t];
    float4 n;
    n.x = f * np.x + ip * kv.x;
    n.y = f * np.y + ip * kv.y;
    n.z = f * np.z + ip * kv.z;
    n.w = f * np.w + ip * kv.w;
    ((float4*)(out_n + (size_t)b * DH))[t] = n;

    float s = n.x * qv.x + n.y * qv.y + n.z * qv.z + n.w * qv.w;
    s = warp_sum(s);
    if ((t & 31) == 0) sbi[t >> 5] = s;
    __syncthreads();
    if (t == 0) {
        float tot = 0.f;
        #pragma unroll
        for (int w = 0; w < 8; w++) tot += sbi[w];
        g_den[b] = fmaxf(fabsf(tot), 1.f);
    }
}

// ============================================================
// Fused C update + Cq matvec + h_head  (HBM-bound)
// grid (64 row-chunks, 128 batches), 512 threads = 16 warps.
// Warp w owns row i: 8 LDG.128.cs batched (MLP=8), FMA,
// streaming stores, warp-reduced dot with q.
// ============================================================
__global__ void __launch_bounds__(512)
c_update_kernel(const float* __restrict__ Cprev, float* __restrict__ Cout)
{
    const int b = blockIdx.y;
    __shared__ float4 ks4[256];
    __shared__ float4 qs4[256];
    if (threadIdx.x < 256) {
        const int t = threadIdx.x;
        ks4[t] = ((const float4*)(g_k + (size_t)b * DH))[t];
        qs4[t] = ((const float4*)(g_q + (size_t)b * DH))[t];
    }
    __syncthreads();

    const int warp = threadIdx.x >> 5;
    const int lane = threadIdx.x & 31;
    const int i = blockIdx.x * 16 + warp;

    const float f  = g_fp[b];
    const float iv = g_ip[b] * g_v[(size_t)b * DH + i];

    const float4* __restrict__ cp = (const float4*)(Cprev + ((size_t)b * DH + i) * DH);
    float4* __restrict__ co = (float4*)(Cout + ((size_t)b * DH + i) * DH);

    float4 c[8];
    #pragma unroll
    for (int u = 0; u < 8; u++) c[u] = __ldcs(&cp[u * 32 + lane]);

    float acc = 0.f;
    #pragma unroll
    for (int u = 0; u < 8; u++) {
        const int j4 = u * 32 + lane;
        const float4 k4 = ks4[j4];
        const float4 q4 = qs4[j4];
        float4 o;
        o.x = fmaf(f, c[u].x, iv * k4.x);
        o.y = fmaf(f, c[u].y, iv * k4.y);
        o.z = fmaf(f, c[u].z, iv * k4.z);
        o.w = fmaf(f, c[u].w, iv * k4.w);
        acc = fmaf(o.x, q4.x, acc);
        acc = fmaf(o.y, q4.y, acc);
        acc = fmaf(o.z, q4.z, acc);
        acc = fmaf(o.w, q4.w, acc);
        __stcs(&co[j4], o);
    }
    acc = warp_sum(acc);
    if (lane == 0)
        g_hh[(size_t)b * DH + i] = g_o[(size_t)b * DH + i] * acc / g_den[b];
}

// ============================================================
// out_proj split-K: grid (32 n, 2 m, 4 ksplit), 128 thr
// BM=64, BN=32, BK=16, 4x4 tile, K-range 256 per split
// ============================================================
__global__ void __launch_bounds__(128)
outproj_kernel(const float* __restrict__ P)
{
    __shared__ float Xs[2][16][SMS];
    __shared__ float Ws[2][16][36];

    const int z  = blockIdx.z;
    const int m0 = blockIdx.y * 64;
    const int n0 = blockIdx.x * 32;
    const int tid = threadIdx.x;
    const int tx = tid & 7;
    const int ty = tid >> 3;

    const int xr = tid >> 1, xc = tid & 1;
    const int wr = tid >> 2, wc = tid & 3;
    const int kbeg = z * 256;

    const float* __restrict__ xg = g_hh + (size_t)(m0 + xr) * DH + kbeg + xc * 8;
    const float* __restrict__ wg = P    + (size_t)(n0 + wr) * DH + kbeg + wc * 4;

    float4 xv0 = *(const float4*)xg;
    float4 xv1 = *(const float4*)(xg + 4);
    float4 wv  = *(const float4*)wg;

    float acc[4][4] = {};
    int buf = 0;

    #pragma unroll 1
    for (int kt = 0; kt < 16; kt++) {
        {
            const int cb = xc * 8;
            Xs[buf][cb + 0][xr] = xv0.x; Xs[buf][cb + 1][xr] = xv0.y;
            Xs[buf][cb + 2][xr] = xv0.z; Xs[buf][cb + 3][xr] = xv0.w;
            Xs[buf][cb + 4][xr] = xv1.x; Xs[buf][cb + 5][xr] = xv1.y;
            Xs[buf][cb + 6][xr] = xv1.z; Xs[buf][cb + 7][xr] = xv1.w;
            Ws[buf][wc * 4 + 0][wr] = wv.x; Ws[buf][wc * 4 + 1][wr] = wv.y;
            Ws[buf][wc * 4 + 2][wr] = wv.z; Ws[buf][wc * 4 + 3][wr] = wv.w;
        }
        __syncthreads();
        if (kt + 1 < 16) {
            xv0 = *(const float4*)(xg + (kt + 1) * 16);
            xv1 = *(const float4*)(xg + (kt + 1) * 16 + 4);
            wv  = *(const float4*)(wg + (kt + 1) * 16);
        }
        #pragma unroll
        for (int k = 0; k < 16; k++) {
            const float4 a = *(const float4*)&Xs[buf][k][ty * 4];
            const float4 w = *(const float4*)&Ws[buf][k][tx * 4];
            acc[0][0] = fmaf(a.x, w.x, acc[0][0]); acc[0][1] = fmaf(a.x, w.y, acc[0][1]);
            acc[0][2] = fmaf(a.x, w.z, acc[0][2]); acc[0][3] = fmaf(a.x, w.w, acc[0][3]);
            acc[1][0] = fmaf(a.y, w.x, acc[1][0]); acc[1][1] = fmaf(a.y, w.y, acc[1][1]);
            acc[1][2] = fmaf(a.y, w.z, acc[1][2]); acc[1][3] = fmaf(a.y, w.w, acc[1][3]);
            acc[2][0] = fmaf(a.z, w.x, acc[2][0]); acc[2][1] = fmaf(a.z, w.y, acc[2][1]);
            acc[2][2] = fmaf(a.z, w.z, acc[2][2]); acc[2][3] = fmaf(a.z, w.w, acc[2][3]);
            acc[3][0] = fmaf(a.w, w.x, acc[3][0]); acc[3][1] = fmaf(a.w, w.y, acc[3][1]);
            acc[3][2] = fmaf(a.w, w.z, acc[3][2]); acc[3][3] = fmaf(a.w, w.w, acc[3][3]);
        }
        __syncthreads();
        buf ^= 1;
    }

    float* __restrict__ Yp = g_part[z];
    #pragma unroll
    for (int i = 0; i < 4; i++) {
        const int m = m0 + ty * 4 + i;
        const int nb = n0 + tx * 4;
        float4 y;
        y.x = acc[i][0]; y.y = acc[i][1]; y.z = acc[i][2]; y.w = acc[i][3];
        *(float4*)&Yp[(size_t)m * DM + nb] = y;
    }
}

__global__ void __launch_bounds__(256)
outproj_reduce_kernel(float* __restrict__ out_h)
{
    const int idx = blockIdx.x * 256 + threadIdx.x; // float4 index
    const float4 a = ((const float4*)g_part[0])[idx];
    const float4 b = ((const float4*)g_part[1])[idx];
    const float4 c = ((const float4*)g_part[2])[idx];
    const float4 d = ((const float4*)g_part[3])[idx];
    float4 r;
    r.x = (a.x + b.x) + (c.x + d.x);
    r.y = (a.y + b.y) + (c.y + d.y);
    r.z = (a.z + b.z) + (c.z + d.z);
    r.w = (a.w + b.w) + (c.w + d.w);
    ((float4*)out_h)[idx] = r;
}

// ============================================================
// launch
// ============================================================
extern "C" void kernel_launch(void* const* d_in, const int* in_sizes, int n_in,
                              void* d_out, int out_size)
{
    const float* x     = (const float*)d_in[0];
    const float* Cprev = (const float*)d_in[1];
    const float* nprev = (const float*)d_in[2];
    const float* mprev = (const float*)d_in[3];
    const float* Wq    = (const float*)d_in[4];
    const float* Wk    = (const float*)d_in[5];
    const float* Wv    = (const float*)d_in[6];
    const float* wi    = (const float*)d_in[7];
    const float* wib   = (const float*)d_in[8];
    const float* wf    = (const float*)d_in[9];
    const float* wfb   = (const float*)d_in[10];
    const float* Wo    = (const float*)d_in[11];
    const float* Wob   = (const float*)d_in[12];
    const float* P     = (const float*)d_in[13];

    float* out   = (float*)d_out;
    float* out_h = out;                                        // (B, 1024)
    float* out_c = out + (size_t)BATCH * DM;                   // (B, 1024, 1024)
    float* out_n = out_c + (size_t)BATCH * DH * DH;            // (B, 1024)
    float* out_m = out_n + (size_t)BATCH * DH;                 // (B,)

    proj_kernel<<<dim3(32, 2, 4), 128>>>(x, Wq, Wk, Wv, Wo, Wob);
    gate_ndenom_kernel<<<BATCH, 256>>>(x, wi, wib, wf, wfb, mprev, nprev, out_m, out_n);
    c_update_kernel<<<dim3(64, BATCH), 512>>>(Cprev, out_c);
    outproj_kernel<<<dim3(32, 2, 4), 128>>>(P);
    outproj_reduce_kernel<<<128, 256>>>(out_h);
}